// round 1
// baseline (speedup 1.0000x reference)
#include <cuda_runtime.h>

// Device-global scratch (no allocations allowed).
static __device__ double g_acc[9];   // S0,S1,S2, P00,P11,P22, P01,P02,P12
static __device__ float  g_par[12];  // basis rows (right,up,fwd) row-major [9], refPos [3]

__global__ void k_zero() {
    int i = threadIdx.x;
    if (i < 9) g_acc[i] = 0.0;
}

// Pass 1: 9 reductions over rows 0..2, plus copy rows 7..9 -> out rows 3..5.
__global__ void __launch_bounds__(256) k_reduce_copy(const float* __restrict__ x,
                                                     float* __restrict__ out, int T) {
    const int nv = T >> 2;
    const size_t Ts = (size_t)T;
    const float4* __restrict__ x0 = (const float4*)(x);
    const float4* __restrict__ x1 = (const float4*)(x + Ts);
    const float4* __restrict__ x2 = (const float4*)(x + 2 * Ts);
    const float4* __restrict__ a0 = (const float4*)(x + 7 * Ts);
    const float4* __restrict__ a1 = (const float4*)(x + 8 * Ts);
    const float4* __restrict__ a2 = (const float4*)(x + 9 * Ts);
    float4* __restrict__ o3 = (float4*)(out + 3 * Ts);
    float4* __restrict__ o4 = (float4*)(out + 4 * Ts);
    float4* __restrict__ o5 = (float4*)(out + 5 * Ts);

    float acc[9];
#pragma unroll
    for (int k = 0; k < 9; ++k) acc[k] = 0.0f;

    const int gid = blockIdx.x * blockDim.x + threadIdx.x;
    const int stride = gridDim.x * blockDim.x;

    for (int i = gid; i < nv; i += stride) {
        float4 v0 = x0[i], v1 = x1[i], v2 = x2[i];
        float c0[4] = {v0.x, v0.y, v0.z, v0.w};
        float c1[4] = {v1.x, v1.y, v1.z, v1.w};
        float c2[4] = {v2.x, v2.y, v2.z, v2.w};
#pragma unroll
        for (int k = 0; k < 4; ++k) {
            float a = c0[k], b = c1[k], c = c2[k];
            acc[0] += a;     acc[1] += b;     acc[2] += c;
            acc[3] += a * a; acc[4] += b * b; acc[5] += c * c;
            acc[6] += a * b; acc[7] += a * c; acc[8] += b * c;
        }
        o3[i] = a0[i];
        o4[i] = a1[i];
        o5[i] = a2[i];
    }
    // Scalar tail (T % 4 != 0 safety; T=4M is divisible).
    for (int t = (nv << 2) + gid; t < T; t += stride) {
        float a = x[t], b = x[Ts + t], c = x[2 * Ts + t];
        acc[0] += a;     acc[1] += b;     acc[2] += c;
        acc[3] += a * a; acc[4] += b * b; acc[5] += c * c;
        acc[6] += a * b; acc[7] += a * c; acc[8] += b * c;
        out[3 * Ts + t] = x[7 * Ts + t];
        out[4 * Ts + t] = x[8 * Ts + t];
        out[5 * Ts + t] = x[9 * Ts + t];
    }

    // Warp reduce (fp32 partials are tiny: ~16 columns/thread).
#pragma unroll
    for (int k = 0; k < 9; ++k) {
        float v = acc[k];
#pragma unroll
        for (int off = 16; off > 0; off >>= 1)
            v += __shfl_down_sync(0xffffffffu, v, off);
        acc[k] = v;
    }
    __shared__ float ws[9][8];
    const int lane = threadIdx.x & 31, warp = threadIdx.x >> 5;
    if (lane == 0) {
#pragma unroll
        for (int k = 0; k < 9; ++k) ws[k][warp] = acc[k];
    }
    __syncthreads();
    if (threadIdx.x == 0) {
#pragma unroll
        for (int k = 0; k < 9; ++k) {
            double d = 0.0;
#pragma unroll
            for (int w = 0; w < 8; ++w) d += (double)ws[k][w];
            atomicAdd(&g_acc[k], d);
        }
    }
}

// Pass 2 (tiny): covariance -> Jacobi eigensolve (double) -> basis.
__global__ void k_solve(const float* __restrict__ x, const float* __restrict__ ra, int T) {
    if (threadIdx.x != 0 || blockIdx.x != 0) return;
    const size_t Ts = (size_t)T;
    const double Tn = (double)T;
    const double S0 = g_acc[0], S1 = g_acc[1], S2 = g_acc[2];
    double A[3][3];
    A[0][0] = (g_acc[3] - S0 * S0 / Tn) / (Tn - 1.0);
    A[1][1] = (g_acc[4] - S1 * S1 / Tn) / (Tn - 1.0);
    A[2][2] = (g_acc[5] - S2 * S2 / Tn) / (Tn - 1.0);
    A[0][1] = A[1][0] = (g_acc[6] - S0 * S1 / Tn) / (Tn - 1.0);
    A[0][2] = A[2][0] = (g_acc[7] - S0 * S2 / Tn) / (Tn - 1.0);
    A[1][2] = A[2][1] = (g_acc[8] - S1 * S2 / Tn) / (Tn - 1.0);

    double V[3][3] = {{1, 0, 0}, {0, 1, 0}, {0, 0, 1}};
    for (int sweep = 0; sweep < 64; ++sweep) {
        double off = fabs(A[0][1]) + fabs(A[0][2]) + fabs(A[1][2]);
        if (off == 0.0) break;
        for (int p = 0; p < 2; ++p) {
            for (int q = p + 1; q < 3; ++q) {
                double apq = A[p][q];
                if (fabs(apq) < 1e-300) continue;
                double theta = (A[q][q] - A[p][p]) / (2.0 * apq);
                double t = 1.0 / (fabs(theta) + sqrt(theta * theta + 1.0));
                if (theta < 0.0) t = -t;
                double c = 1.0 / sqrt(t * t + 1.0);
                double s = t * c;
                double app = A[p][p], aqq = A[q][q];
                A[p][p] = app - t * apq;
                A[q][q] = aqq + t * apq;
                A[p][q] = A[q][p] = 0.0;
                int r = 3 - p - q;
                double arp = A[r][p], arq = A[r][q];
                A[r][p] = A[p][r] = c * arp - s * arq;
                A[r][q] = A[q][r] = s * arp + c * arq;
                for (int i = 0; i < 3; ++i) {
                    double vip = V[i][p], viq = V[i][q];
                    V[i][p] = c * vip - s * viq;
                    V[i][q] = s * vip + c * viq;
                }
            }
        }
    }
    int m = 0;
    if (A[1][1] > A[m][m]) m = 1;
    if (A[2][2] > A[m][m]) m = 2;
    double vz0 = V[0][m], vz1 = V[1][m], vz2 = V[2][m];

    // ZFwd = quat-rotate (0,0,1) with q = x[3..6][t=0]
    double qx = (double)x[3 * Ts], qy = (double)x[4 * Ts];
    double qz = (double)x[5 * Ts], qw = (double)x[6 * Ts];
    double zfx = 2.0 * (qx * qz + qw * qy);
    double zfy = 2.0 * (qy * qz - qw * qx);
    double zfz = 1.0 - 2.0 * (qx * qx + qy * qy);
    if (zfx * vz0 + zfy * vz1 + zfz * vz2 < 0.0) { vz0 = -vz0; vz1 = -vz1; vz2 = -vz2; }

    double ux = (double)ra[0], uy = (double)ra[1], uz = (double)ra[2];
    // right = up x pca_z
    double rx = uy * vz2 - uz * vz1;
    double ry = uz * vz0 - ux * vz2;
    double rz = ux * vz1 - uy * vz0;
    // fwd = right x up
    double fx = ry * uz - rz * uy;
    double fy = rz * ux - rx * uz;
    double fz = rx * uy - ry * ux;

    g_par[0] = (float)rx; g_par[1] = (float)ry; g_par[2] = (float)rz;
    g_par[3] = (float)ux; g_par[4] = (float)uy; g_par[5] = (float)uz;
    g_par[6] = (float)fx; g_par[7] = (float)fy; g_par[8] = (float)fz;
    g_par[9]  = x[0];
    g_par[10] = x[Ts];
    g_par[11] = x[2 * Ts];
}

// Pass 3: out rows 0..2 = basis * (Xpos - refPos)
__global__ void __launch_bounds__(256) k_transform(const float* __restrict__ x,
                                                   float* __restrict__ out, int T) {
    const int nv = T >> 2;
    const size_t Ts = (size_t)T;
    const float b00 = g_par[0], b01 = g_par[1], b02 = g_par[2];
    const float b10 = g_par[3], b11 = g_par[4], b12 = g_par[5];
    const float b20 = g_par[6], b21 = g_par[7], b22 = g_par[8];
    const float r0 = g_par[9], r1 = g_par[10], r2 = g_par[11];

    const float4* __restrict__ x0 = (const float4*)(x);
    const float4* __restrict__ x1 = (const float4*)(x + Ts);
    const float4* __restrict__ x2 = (const float4*)(x + 2 * Ts);
    float4* __restrict__ o0 = (float4*)(out);
    float4* __restrict__ o1 = (float4*)(out + Ts);
    float4* __restrict__ o2 = (float4*)(out + 2 * Ts);

    const int gid = blockIdx.x * blockDim.x + threadIdx.x;
    const int stride = gridDim.x * blockDim.x;

    for (int i = gid; i < nv; i += stride) {
        float4 v0 = x0[i], v1 = x1[i], v2 = x2[i];
        float c0[4] = {v0.x, v0.y, v0.z, v0.w};
        float c1[4] = {v1.x, v1.y, v1.z, v1.w};
        float c2[4] = {v2.x, v2.y, v2.z, v2.w};
        float w0[4], w1[4], w2[4];
#pragma unroll
        for (int k = 0; k < 4; ++k) {
            float d0 = c0[k] - r0, d1 = c1[k] - r1, d2 = c2[k] - r2;
            w0[k] = b00 * d0 + b01 * d1 + b02 * d2;
            w1[k] = b10 * d0 + b11 * d1 + b12 * d2;
            w2[k] = b20 * d0 + b21 * d1 + b22 * d2;
        }
        o0[i] = make_float4(w0[0], w0[1], w0[2], w0[3]);
        o1[i] = make_float4(w1[0], w1[1], w1[2], w1[3]);
        o2[i] = make_float4(w2[0], w2[1], w2[2], w2[3]);
    }
    for (int t = (nv << 2) + gid; t < T; t += stride) {
        float d0 = x[t] - r0, d1 = x[Ts + t] - r1, d2 = x[2 * Ts + t] - r2;
        out[t]          = b00 * d0 + b01 * d1 + b02 * d2;
        out[Ts + t]     = b10 * d0 + b11 * d1 + b12 * d2;
        out[2 * Ts + t] = b20 * d0 + b21 * d1 + b22 * d2;
    }
}

extern "C" void kernel_launch(void* const* d_in, const int* in_sizes, int n_in,
                              void* d_out, int out_size) {
    const float* x  = (const float*)d_in[0];
    const float* ra = (const float*)d_in[1];
    float* out = (float*)d_out;
    const int T = in_sizes[0] / 10;
    const int nv = T >> 2;

    int blocks = 1184;  // 148 SMs x 8
    int needed = (nv + 255) / 256;
    if (blocks > needed) blocks = needed;
    if (blocks < 1) blocks = 1;

    k_zero<<<1, 32>>>();
    k_reduce_copy<<<blocks, 256>>>(x, out, T);
    k_solve<<<1, 1>>>(x, ra, T);
    k_transform<<<blocks, 256>>>(x, out, T);
}

// round 2
// speedup vs baseline: 1.1890x; 1.1890x over previous
#include <cuda_runtime.h>

// Device-global scratch (no allocations allowed).
static __device__ double g_acc[9];   // S0,S1,S2, P00,P11,P22, P01,P02,P12
static __device__ float  g_par[12];  // basis rows (right,up,fwd) row-major [9], refPos [3]

__global__ void k_zero() {
    int i = threadIdx.x;
    if (i < 9) g_acc[i] = 0.0;
}

// Pass 1: 9 reductions over rows 0..2, plus copy rows 7..9 -> out rows 3..5.
__global__ void __launch_bounds__(256) k_reduce_copy(const float* __restrict__ x,
                                                     float* __restrict__ out, int T) {
    const int nv = T >> 2;
    const size_t Ts = (size_t)T;
    const float4* __restrict__ x0 = (const float4*)(x);
    const float4* __restrict__ x1 = (const float4*)(x + Ts);
    const float4* __restrict__ x2 = (const float4*)(x + 2 * Ts);
    const float4* __restrict__ a0 = (const float4*)(x + 7 * Ts);
    const float4* __restrict__ a1 = (const float4*)(x + 8 * Ts);
    const float4* __restrict__ a2 = (const float4*)(x + 9 * Ts);
    float4* __restrict__ o3 = (float4*)(out + 3 * Ts);
    float4* __restrict__ o4 = (float4*)(out + 4 * Ts);
    float4* __restrict__ o5 = (float4*)(out + 5 * Ts);

    float acc[9];
#pragma unroll
    for (int k = 0; k < 9; ++k) acc[k] = 0.0f;

    const int gid = blockIdx.x * blockDim.x + threadIdx.x;
    const int stride = gridDim.x * blockDim.x;

    for (int i = gid; i < nv; i += stride) {
        float4 v0 = x0[i], v1 = x1[i], v2 = x2[i];
        float c0[4] = {v0.x, v0.y, v0.z, v0.w};
        float c1[4] = {v1.x, v1.y, v1.z, v1.w};
        float c2[4] = {v2.x, v2.y, v2.z, v2.w};
#pragma unroll
        for (int k = 0; k < 4; ++k) {
            float a = c0[k], b = c1[k], c = c2[k];
            acc[0] += a;     acc[1] += b;     acc[2] += c;
            acc[3] += a * a; acc[4] += b * b; acc[5] += c * c;
            acc[6] += a * b; acc[7] += a * c; acc[8] += b * c;
        }
        o3[i] = a0[i];
        o4[i] = a1[i];
        o5[i] = a2[i];
    }
    // Scalar tail (T % 4 != 0 safety; T=4M is divisible).
    for (int t = (nv << 2) + gid; t < T; t += stride) {
        float a = x[t], b = x[Ts + t], c = x[2 * Ts + t];
        acc[0] += a;     acc[1] += b;     acc[2] += c;
        acc[3] += a * a; acc[4] += b * b; acc[5] += c * c;
        acc[6] += a * b; acc[7] += a * c; acc[8] += b * c;
        out[3 * Ts + t] = x[7 * Ts + t];
        out[4 * Ts + t] = x[8 * Ts + t];
        out[5 * Ts + t] = x[9 * Ts + t];
    }

    // Warp reduce (fp32 partials are tiny: ~16 columns/thread).
#pragma unroll
    for (int k = 0; k < 9; ++k) {
        float v = acc[k];
#pragma unroll
        for (int off = 16; off > 0; off >>= 1)
            v += __shfl_down_sync(0xffffffffu, v, off);
        acc[k] = v;
    }
    __shared__ float ws[9][8];
    const int lane = threadIdx.x & 31, warp = threadIdx.x >> 5;
    if (lane == 0) {
#pragma unroll
        for (int k = 0; k < 9; ++k) ws[k][warp] = acc[k];
    }
    __syncthreads();
    if (threadIdx.x == 0) {
#pragma unroll
        for (int k = 0; k < 9; ++k) {
            double d = 0.0;
#pragma unroll
            for (int w = 0; w < 8; ++w) d += (double)ws[k][w];
            atomicAdd(&g_acc[k], d);
        }
    }
}

// Pass 2 (tiny): covariance -> Jacobi eigensolve (double) -> basis.
// Early-exit as soon as off-diagonal mass is negligible: Jacobi converges
// quadratically (4-5 sweeps here); dead sweeps in serial FP64 cost ~0.7us each.
__global__ void k_solve(const float* __restrict__ x, const float* __restrict__ ra, int T) {
    if (threadIdx.x != 0 || blockIdx.x != 0) return;
    const size_t Ts = (size_t)T;
    const double Tn = (double)T;
    const double S0 = g_acc[0], S1 = g_acc[1], S2 = g_acc[2];
    double A[3][3];
    A[0][0] = (g_acc[3] - S0 * S0 / Tn) / (Tn - 1.0);
    A[1][1] = (g_acc[4] - S1 * S1 / Tn) / (Tn - 1.0);
    A[2][2] = (g_acc[5] - S2 * S2 / Tn) / (Tn - 1.0);
    A[0][1] = A[1][0] = (g_acc[6] - S0 * S1 / Tn) / (Tn - 1.0);
    A[0][2] = A[2][0] = (g_acc[7] - S0 * S2 / Tn) / (Tn - 1.0);
    A[1][2] = A[2][1] = (g_acc[8] - S1 * S2 / Tn) / (Tn - 1.0);

    const double scale = fabs(A[0][0]) + fabs(A[1][1]) + fabs(A[2][2]) + 1e-300;
    double V[3][3] = {{1, 0, 0}, {0, 1, 0}, {0, 0, 1}};
    for (int sweep = 0; sweep < 8; ++sweep) {
        double off = fabs(A[0][1]) + fabs(A[0][2]) + fabs(A[1][2]);
        if (off < 1e-14 * scale) break;   // converged to double precision
        for (int p = 0; p < 2; ++p) {
            for (int q = p + 1; q < 3; ++q) {
                double apq = A[p][q];
                if (fabs(apq) < 1e-200) continue;
                double theta = (A[q][q] - A[p][p]) / (2.0 * apq);
                double t = 1.0 / (fabs(theta) + sqrt(theta * theta + 1.0));
                if (theta < 0.0) t = -t;
                double c = 1.0 / sqrt(t * t + 1.0);
                double s = t * c;
                double app = A[p][p], aqq = A[q][q];
                A[p][p] = app - t * apq;
                A[q][q] = aqq + t * apq;
                A[p][q] = A[q][p] = 0.0;
                int r = 3 - p - q;
                double arp = A[r][p], arq = A[r][q];
                A[r][p] = A[p][r] = c * arp - s * arq;
                A[r][q] = A[q][r] = s * arp + c * arq;
                for (int i = 0; i < 3; ++i) {
                    double vip = V[i][p], viq = V[i][q];
                    V[i][p] = c * vip - s * viq;
                    V[i][q] = s * vip + c * viq;
                }
            }
        }
    }
    int m = 0;
    if (A[1][1] > A[m][m]) m = 1;
    if (A[2][2] > A[m][m]) m = 2;
    double vz0 = V[0][m], vz1 = V[1][m], vz2 = V[2][m];

    // ZFwd = quat-rotate (0,0,1) with q = x[3..6][t=0]
    double qx = (double)x[3 * Ts], qy = (double)x[4 * Ts];
    double qz = (double)x[5 * Ts], qw = (double)x[6 * Ts];
    double zfx = 2.0 * (qx * qz + qw * qy);
    double zfy = 2.0 * (qy * qz - qw * qx);
    double zfz = 1.0 - 2.0 * (qx * qx + qy * qy);
    if (zfx * vz0 + zfy * vz1 + zfz * vz2 < 0.0) { vz0 = -vz0; vz1 = -vz1; vz2 = -vz2; }

    double ux = (double)ra[0], uy = (double)ra[1], uz = (double)ra[2];
    // right = up x pca_z
    double rx = uy * vz2 - uz * vz1;
    double ry = uz * vz0 - ux * vz2;
    double rz = ux * vz1 - uy * vz0;
    // fwd = right x up
    double fx = ry * uz - rz * uy;
    double fy = rz * ux - rx * uz;
    double fz = rx * uy - ry * ux;

    g_par[0] = (float)rx; g_par[1] = (float)ry; g_par[2] = (float)rz;
    g_par[3] = (float)ux; g_par[4] = (float)uy; g_par[5] = (float)uz;
    g_par[6] = (float)fx; g_par[7] = (float)fy; g_par[8] = (float)fz;
    g_par[9]  = x[0];
    g_par[10] = x[Ts];
    g_par[11] = x[2 * Ts];
}

// Pass 3: out rows 0..2 = basis * (Xpos - refPos)
__global__ void __launch_bounds__(256) k_transform(const float* __restrict__ x,
                                                   float* __restrict__ out, int T) {
    const int nv = T >> 2;
    const size_t Ts = (size_t)T;
    const float b00 = g_par[0], b01 = g_par[1], b02 = g_par[2];
    const float b10 = g_par[3], b11 = g_par[4], b12 = g_par[5];
    const float b20 = g_par[6], b21 = g_par[7], b22 = g_par[8];
    const float r0 = g_par[9], r1 = g_par[10], r2 = g_par[11];

    const float4* __restrict__ x0 = (const float4*)(x);
    const float4* __restrict__ x1 = (const float4*)(x + Ts);
    const float4* __restrict__ x2 = (const float4*)(x + 2 * Ts);
    float4* __restrict__ o0 = (float4*)(out);
    float4* __restrict__ o1 = (float4*)(out + Ts);
    float4* __restrict__ o2 = (float4*)(out + 2 * Ts);

    const int gid = blockIdx.x * blockDim.x + threadIdx.x;
    const int stride = gridDim.x * blockDim.x;

    for (int i = gid; i < nv; i += stride) {
        float4 v0 = x0[i], v1 = x1[i], v2 = x2[i];
        float c0[4] = {v0.x, v0.y, v0.z, v0.w};
        float c1[4] = {v1.x, v1.y, v1.z, v1.w};
        float c2[4] = {v2.x, v2.y, v2.z, v2.w};
        float w0[4], w1[4], w2[4];
#pragma unroll
        for (int k = 0; k < 4; ++k) {
            float d0 = c0[k] - r0, d1 = c1[k] - r1, d2 = c2[k] - r2;
            w0[k] = b00 * d0 + b01 * d1 + b02 * d2;
            w1[k] = b10 * d0 + b11 * d1 + b12 * d2;
            w2[k] = b20 * d0 + b21 * d1 + b22 * d2;
        }
        o0[i] = make_float4(w0[0], w0[1], w0[2], w0[3]);
        o1[i] = make_float4(w1[0], w1[1], w1[2], w1[3]);
        o2[i] = make_float4(w2[0], w2[1], w2[2], w2[3]);
    }
    for (int t = (nv << 2) + gid; t < T; t += stride) {
        float d0 = x[t] - r0, d1 = x[Ts + t] - r1, d2 = x[2 * Ts + t] - r2;
        out[t]          = b00 * d0 + b01 * d1 + b02 * d2;
        out[Ts + t]     = b10 * d0 + b11 * d1 + b12 * d2;
        out[2 * Ts + t] = b20 * d0 + b21 * d1 + b22 * d2;
    }
}

extern "C" void kernel_launch(void* const* d_in, const int* in_sizes, int n_in,
                              void* d_out, int out_size) {
    const float* x  = (const float*)d_in[0];
    const float* ra = (const float*)d_in[1];
    float* out = (float*)d_out;
    const int T = in_sizes[0] / 10;
    const int nv = T >> 2;

    int blocks = 1184;  // 148 SMs x 8
    int needed = (nv + 255) / 256;
    if (blocks > needed) blocks = needed;
    if (blocks < 1) blocks = 1;

    k_zero<<<1, 32>>>();
    k_reduce_copy<<<blocks, 256>>>(x, out, T);
    k_solve<<<1, 1>>>(x, ra, T);
    k_transform<<<blocks, 256>>>(x, out, T);
}